// round 6
// baseline (speedup 1.0000x reference)
#include <cuda_runtime.h>
#include <cuda_bf16.h>
#include <cstdint>

// DeChunkLayer collapses to a gather:
//   cum[b,s]   = inclusive cumsum of boundary_mask along s
//   out[b,s,:] = cum>0 ? compressed_states[b, cum-1, :] : 0
// Fused single kernel: each block recomputes its prefix count from the
// (L2-resident) mask, then gathers 16 output rows. All 16 loads are in
// flight before the first store (MLP=16); stores are evict-first (__stcs)
// so L2 stays dedicated to gather-read reuse.

#define B_ 8
#define S_ 4096
#define D_ 1024
#define ROWS_PER_BLK 16

__global__ void __launch_bounds__(256)
fused_kernel(const float* __restrict__ cs,
             const int* __restrict__ mask,
             float* __restrict__ out)
{
    const int base = blockIdx.x * ROWS_PER_BLK;   // global (b*S+s) of first row
    const int b    = base >> 12;                  // / S_
    const int s0   = base & (S_ - 1);             // row within batch (mult of 16)
    const int t    = threadIdx.x;
    const int lane = t & 31;
    const int warp = t >> 5;

    const int* mrow = mask + (size_t)b * S_;

    // ---- 1) count boundaries in [0, s0) --------------------------------
    int cnt = 0;
    const int4* m4 = reinterpret_cast<const int4*>(mrow);
    for (int i = t; i < (s0 >> 2); i += 256) {
        int4 v = __ldg(&m4[i]);
        cnt += (v.x != 0) + (v.y != 0) + (v.z != 0) + (v.w != 0);
    }
    #pragma unroll
    for (int o = 16; o; o >>= 1)
        cnt += __shfl_xor_sync(0xffffffffu, cnt, o);

    __shared__ int ws[8];
    __shared__ int rows[ROWS_PER_BLK];
    if (lane == 0) ws[warp] = cnt;
    __syncthreads();

    // ---- 2) warp 0: total + inclusive scan of this block's 16 mask bits
    if (warp == 0) {
        int v = (lane < 8) ? ws[lane] : 0;
        #pragma unroll
        for (int o = 4; o; o >>= 1)
            v += __shfl_xor_sync(0xffffffffu, v, o);      // lanes 0..7 -> total
        int total = __shfl_sync(0xffffffffu, v, 0);

        int m = (lane < ROWS_PER_BLK) ? (mrow[s0 + lane] != 0) : 0;
        int incl = m;
        #pragma unroll
        for (int o = 1; o < ROWS_PER_BLK; o <<= 1) {
            int n = __shfl_up_sync(0xffffffffu, incl, o);
            if (lane >= o) incl += n;
        }
        if (lane < ROWS_PER_BLK)
            rows[lane] = total + incl - 1;                // -1 => emit zeros
    }
    __syncthreads();

    // ---- 3) gather 16 rows; all loads in flight before first store -----
    const float4* cs4 = reinterpret_cast<const float4*>(cs) + (size_t)b * (S_ * 256);
    float4* o4 = reinterpret_cast<float4*>(out) + (size_t)base * 256 + t;

    float4 va[8], vb[8];
    #pragma unroll
    for (int r = 0; r < 8; r++) {
        int row = rows[r];
        va[r] = (row < 0) ? make_float4(0.f, 0.f, 0.f, 0.f)
                          : __ldg(cs4 + (size_t)row * 256 + t);
    }
    #pragma unroll
    for (int r = 0; r < 8; r++) {
        int row = rows[8 + r];
        vb[r] = (row < 0) ? make_float4(0.f, 0.f, 0.f, 0.f)
                          : __ldg(cs4 + (size_t)row * 256 + t);
    }
    #pragma unroll
    for (int r = 0; r < 8; r++)
        __stcs(o4 + (size_t)r * 256, va[r]);
    #pragma unroll
    for (int r = 0; r < 8; r++)
        __stcs(o4 + (size_t)(8 + r) * 256, vb[r]);
}

// ---------------------------------------------------------------------------
extern "C" void kernel_launch(void* const* d_in, const int* in_sizes, int n_in,
                              void* d_out, int out_size)
{
    const float* cs = nullptr;
    const int*   mask = nullptr;
    for (int i = 0; i < n_in; i++) {
        if (in_sizes[i] == B_ * S_ * D_)      cs   = (const float*)d_in[i];
        else if (in_sizes[i] == B_ * S_)      mask = (const int*)d_in[i];
    }
    float* out = (float*)d_out;

    fused_kernel<<<(B_ * S_) / ROWS_PER_BLK, 256>>>(cs, mask, out);
}

// round 7
// speedup vs baseline: 1.0538x; 1.0538x over previous
#include <cuda_runtime.h>
#include <cuda_bf16.h>
#include <cstdint>

// DeChunkLayer collapses to a gather:
//   cum[b,s]   = inclusive cumsum of boundary_mask along s
//   out[b,s,:] = cum>0 ? compressed_states[b, cum-1, :] : 0
// Fused single kernel, tuned geometry: 8 rows/block (regs ~32 -> high occ),
// MLP=8 float4 loads per thread, plain stores.

#define B_ 8
#define S_ 4096
#define D_ 1024
#define ROWS_PER_BLK 8

__global__ void __launch_bounds__(256)
fused_kernel(const float* __restrict__ cs,
             const int* __restrict__ mask,
             float* __restrict__ out)
{
    const int base = blockIdx.x * ROWS_PER_BLK;   // global (b*S+s) of first row
    const int b    = base >> 12;                  // / S_
    const int s0   = base & (S_ - 1);             // row within batch (mult of 8)
    const int t    = threadIdx.x;
    const int lane = t & 31;
    const int warp = t >> 5;

    const int* mrow = mask + (size_t)b * S_;

    // ---- 1) count boundaries in [0, s0) --------------------------------
    int cnt = 0;
    const int4* m4 = reinterpret_cast<const int4*>(mrow);
    for (int i = t; i < (s0 >> 2); i += 256) {
        int4 v = __ldg(&m4[i]);
        cnt += (v.x != 0) + (v.y != 0) + (v.z != 0) + (v.w != 0);
    }
    #pragma unroll
    for (int o = 16; o; o >>= 1)
        cnt += __shfl_xor_sync(0xffffffffu, cnt, o);

    __shared__ int ws[8];
    __shared__ int rows[ROWS_PER_BLK];
    if (lane == 0) ws[warp] = cnt;
    __syncthreads();

    // ---- 2) warp 0: total + inclusive scan of this block's 8 mask bits -
    if (warp == 0) {
        int v = (lane < 8) ? ws[lane] : 0;
        #pragma unroll
        for (int o = 4; o; o >>= 1)
            v += __shfl_xor_sync(0xffffffffu, v, o);      // lanes 0..7 -> total
        int total = __shfl_sync(0xffffffffu, v, 0);

        int m = (lane < ROWS_PER_BLK) ? (mrow[s0 + lane] != 0) : 0;
        int incl = m;
        #pragma unroll
        for (int o = 1; o < ROWS_PER_BLK; o <<= 1) {
            int n = __shfl_up_sync(0xffffffffu, incl, o);
            if (lane >= o) incl += n;
        }
        if (lane < ROWS_PER_BLK)
            rows[lane] = total + incl - 1;                // -1 => emit zeros
    }
    __syncthreads();

    // ---- 3) gather 8 rows, MLP=8 ---------------------------------------
    const float4* cs4 = reinterpret_cast<const float4*>(cs) + (size_t)b * (S_ * 256);
    float4* o4 = reinterpret_cast<float4*>(out) + (size_t)base * 256 + t;

    float4 v[ROWS_PER_BLK];
    #pragma unroll
    for (int r = 0; r < ROWS_PER_BLK; r++) {
        int row = rows[r];
        v[r] = (row < 0) ? make_float4(0.f, 0.f, 0.f, 0.f)
                         : __ldg(cs4 + (size_t)row * 256 + t);
    }
    #pragma unroll
    for (int r = 0; r < ROWS_PER_BLK; r++)
        o4[(size_t)r * 256] = v[r];
}

// ---------------------------------------------------------------------------
extern "C" void kernel_launch(void* const* d_in, const int* in_sizes, int n_in,
                              void* d_out, int out_size)
{
    const float* cs = nullptr;
    const int*   mask = nullptr;
    for (int i = 0; i < n_in; i++) {
        if (in_sizes[i] == B_ * S_ * D_)      cs   = (const float*)d_in[i];
        else if (in_sizes[i] == B_ * S_)      mask = (const int*)d_in[i];
    }
    float* out = (float*)d_out;

    fused_kernel<<<(B_ * S_) / ROWS_PER_BLK, 256>>>(cs, mask, out);
}